// round 4
// baseline (speedup 1.0000x reference)
#include <cuda_runtime.h>
#include <cstdint>

#define N_MAX 100000
#define E_MAX 3200000
#define TK 64

// ---------------- scratch (static device globals; no allocs) ----------------
__device__ int   d_is64;
__device__ int   d_deg[N_MAX];
__device__ int   d_row[N_MAX + 1];
__device__ int   d_pos[N_MAX];
__device__ int   d_bsum[256];
__device__ int   d_srcs[E_MAX];
__device__ float d_dis[N_MAX];
__device__ float d_g1[(size_t)N_MAX * 16];
__device__ float d_g2[(size_t)N_MAX * 16];

// ---------------- dtype probe: int64 edges have zero high words ----------------
__global__ void k_detect(const int* __restrict__ ei32, int e) {
    if (threadIdx.x == 0 && blockIdx.x == 0) {
        int total32 = 2 * e;               // safe bound under BOTH interpretations
        int stride = (total32 / 2048) * 2; // even stride keeps parity odd
        if (stride < 2) stride = 2;
        int nz = 0;
        for (int k = 0; k < 1024; k++) {
            long long p = 1 + (long long)k * stride;
            if (p >= total32) break;
            nz += (ei32[p] != 0);
        }
        d_is64 = (nz == 0) ? 1 : 0;
    }
}

__device__ __forceinline__ int load_idx(const void* ei, long long pos, int is64) {
    return is64 ? (int)((const long long*)ei)[pos] : ((const int*)ei)[pos];
}

// ---------------- degree + counting sort ----------------
__global__ void k_zero_deg(int n) {
    int i = blockIdx.x * blockDim.x + threadIdx.x;
    if (i < n) d_deg[i] = 0;
}

__global__ void k_count(const void* __restrict__ ei, int e, int n) {
    int i = blockIdx.x * blockDim.x + threadIdx.x;
    if (i < e) {
        int is64 = d_is64;
        int d = load_idx(ei, (long long)e + i, is64);   // dst = second row
        if (d >= 0 && d < n) atomicAdd(&d_deg[d], 1);
    }
}

// block-wise exclusive scan of deg into row, block totals into bsum
__global__ void k_scan_block(int n) {
    __shared__ int sh[1024];
    int i = blockIdx.x * 1024 + threadIdx.x;
    int v = (i < n) ? d_deg[i] : 0;
    sh[threadIdx.x] = v;
    __syncthreads();
    for (int off = 1; off < 1024; off <<= 1) {
        int t = (threadIdx.x >= off) ? sh[threadIdx.x - off] : 0;
        __syncthreads();
        sh[threadIdx.x] += t;
        __syncthreads();
    }
    if (i < n) d_row[i] = sh[threadIdx.x] - v;   // exclusive
    if (threadIdx.x == 1023) d_bsum[blockIdx.x] = sh[1023];
}

__global__ void k_scan_sums(int nb) {
    if (threadIdx.x == 0) {
        int run = 0;
        for (int b = 0; b < nb; b++) { int t = d_bsum[b]; d_bsum[b] = run; run += t; }
        d_bsum[nb] = run;
    }
}

__global__ void k_scan_add(int n, int nb) {
    int i = blockIdx.x * blockDim.x + threadIdx.x;
    if (i < n) {
        int r = d_row[i] + d_bsum[i >> 10];
        d_row[i] = r;
        d_pos[i] = r;
        d_dis[i] = rsqrtf((float)(d_deg[i] + 1));   // +1 = self loop
    }
    if (i == 0) d_row[n] = d_bsum[nb];
}

__global__ void k_place(const void* __restrict__ ei, int e, int n) {
    int i = blockIdx.x * blockDim.x + threadIdx.x;
    if (i < e) {
        int is64 = d_is64;
        int s = load_idx(ei, i, is64);                  // src = first row
        int d = load_idx(ei, (long long)e + i, is64);   // dst = second row
        if (d >= 0 && d < n && s >= 0 && s < n) {
            int p = atomicAdd(&d_pos[d], 1);
            if (p >= 0 && p < E_MAX) d_srcs[p] = s;
        }
    }
}

// ---------------- layer-1 GEMM: g1 = (x @ w1) * dis  (packed f32x2 FMA) ----------------
__global__ void __launch_bounds__(128) k_gemm1(const float* __restrict__ x,
                                               const float* __restrict__ w1, int n) {
    __shared__ float xs[TK][128];      // transposed tile: xs[k][localNode]
    __shared__ float ws[TK * 16];
    int tid = threadIdx.x;
    int node = blockIdx.x * 128 + tid;

    unsigned long long acc[8];
#pragma unroll
    for (int i = 0; i < 8; i++) acc[i] = 0ull;

    for (int kt = 0; kt < 512; kt += TK) {
#pragma unroll
        for (int r = 0; r < 2; r++) {
            int f4 = r * 128 + tid;
            *(float4*)&ws[f4 * 4] = *(const float4*)&w1[kt * 16 + f4 * 4];
        }
#pragma unroll
        for (int r = 0; r < 16; r++) {
            int f4 = r * 128 + tid;          // 0..2047
            int rown = f4 >> 4;              // local node
            int col4 = f4 & 15;              // float4 index within TK
            int gn = blockIdx.x * 128 + rown;
            float4 v = make_float4(0.f, 0.f, 0.f, 0.f);
            if (gn < n) v = *(const float4*)&x[(size_t)gn * 512 + kt + col4 * 4];
            int k0 = col4 * 4;
            xs[k0 + 0][rown] = v.x;
            xs[k0 + 1][rown] = v.y;
            xs[k0 + 2][rown] = v.z;
            xs[k0 + 3][rown] = v.w;
        }
        __syncthreads();
#pragma unroll 8
        for (int k = 0; k < TK; k++) {
            float xv = xs[k][tid];
            unsigned long long xx;
            asm("mov.b64 %0, {%1, %1};" : "=l"(xx) : "f"(xv));
            const unsigned long long* wp = (const unsigned long long*)&ws[k * 16];
#pragma unroll
            for (int q = 0; q < 8; q++)
                asm("fma.rn.f32x2 %0, %1, %2, %0;" : "+l"(acc[q]) : "l"(xx), "l"(wp[q]));
        }
        __syncthreads();
    }

    if (node < n) {
        float di = d_dis[node];
        float outv[16];
#pragma unroll
        for (int q = 0; q < 8; q++) {
            float lo, hi;
            asm("mov.b64 {%0, %1}, %2;" : "=f"(lo), "=f"(hi) : "l"(acc[q]));
            outv[2 * q]     = lo * di;
            outv[2 * q + 1] = hi * di;
        }
#pragma unroll
        for (int q = 0; q < 4; q++)
            *(float4*)&d_g1[(size_t)node * 16 + q * 4] =
                make_float4(outv[4 * q], outv[4 * q + 1], outv[4 * q + 2], outv[4 * q + 3]);
    }
}

// ---------------- gather 1: a1 = relu(dis*(sum g1) + b1); g2 = (a1 @ w2) * dis ----------------
__global__ void k_gather1(const float* __restrict__ b1,
                          const float* __restrict__ w2, int n) {
    __shared__ float w2s[256];
    if (threadIdx.x < 256) w2s[threadIdx.x] = w2[threadIdx.x];
    __syncthreads();

    int t = blockIdx.x * blockDim.x + threadIdx.x;
    int node = t >> 2, c = t & 3;
    bool act = node < n;
    int nc = act ? node : (n - 1);

    int rs = __ldg(&d_row[nc]), re = __ldg(&d_row[nc + 1]);
    float di = __ldg(&d_dis[nc]);
    float4 acc = *(const float4*)&d_g1[(size_t)nc * 16 + c * 4];   // self-loop term
#pragma unroll 4
    for (int e2 = rs; e2 < re; e2++) {
        int s = __ldg(&d_srcs[e2]);
        float4 v = *(const float4*)&d_g1[(size_t)s * 16 + c * 4];
        acc.x += v.x; acc.y += v.y; acc.z += v.z; acc.w += v.w;
    }
    float4 b4 = *(const float4*)&b1[c * 4];
    float al[4];
    al[0] = fmaxf(fmaf(acc.x, di, b4.x), 0.f);
    al[1] = fmaxf(fmaf(acc.y, di, b4.y), 0.f);
    al[2] = fmaxf(fmaf(acc.z, di, b4.z), 0.f);
    al[3] = fmaxf(fmaf(acc.w, di, b4.w), 0.f);

    // 16x16 GEMM via shuffle exchange within aligned group of 4 lanes
    int lane = threadIdx.x & 31;
    int lb = lane & ~3;
    float h2[4] = {0.f, 0.f, 0.f, 0.f};
#pragma unroll
    for (int j = 0; j < 16; j++) {
        float aj = __shfl_sync(0xffffffffu, al[j & 3], lb + (j >> 2));
#pragma unroll
        for (int q = 0; q < 4; q++)
            h2[q] = fmaf(aj, w2s[j * 16 + c * 4 + q], h2[q]);
    }
    if (act)
        *(float4*)&d_g2[(size_t)node * 16 + c * 4] =
            make_float4(h2[0] * di, h2[1] * di, h2[2] * di, h2[3] * di);
}

// ---------------- gather 2: logits + log_softmax ----------------
__global__ void k_gather2(const float* __restrict__ b2, float* __restrict__ out, int n) {
    int t = blockIdx.x * blockDim.x + threadIdx.x;
    int node = t >> 2, c = t & 3;
    bool act = node < n;
    int nc = act ? node : (n - 1);

    int rs = __ldg(&d_row[nc]), re = __ldg(&d_row[nc + 1]);
    float di = __ldg(&d_dis[nc]);
    float4 acc = *(const float4*)&d_g2[(size_t)nc * 16 + c * 4];   // self-loop term
#pragma unroll 4
    for (int e2 = rs; e2 < re; e2++) {
        int s = __ldg(&d_srcs[e2]);
        float4 v = *(const float4*)&d_g2[(size_t)s * 16 + c * 4];
        acc.x += v.x; acc.y += v.y; acc.z += v.z; acc.w += v.w;
    }
    float4 b4 = *(const float4*)&b2[c * 4];
    float l0 = fmaf(acc.x, di, b4.x);
    float l1 = fmaf(acc.y, di, b4.y);
    float l2 = fmaf(acc.z, di, b4.z);
    float l3 = fmaf(acc.w, di, b4.w);

    float m = fmaxf(fmaxf(l0, l1), fmaxf(l2, l3));
    m = fmaxf(m, __shfl_xor_sync(0xffffffffu, m, 1));
    m = fmaxf(m, __shfl_xor_sync(0xffffffffu, m, 2));
    float s4 = expf(l0 - m) + expf(l1 - m) + expf(l2 - m) + expf(l3 - m);
    s4 += __shfl_xor_sync(0xffffffffu, s4, 1);
    s4 += __shfl_xor_sync(0xffffffffu, s4, 2);
    float lse = m + logf(s4);

    if (act)
        *(float4*)&out[(size_t)node * 16 + c * 4] =
            make_float4(l0 - lse, l1 - lse, l2 - lse, l3 - lse);
}

// ---------------- launch ----------------
extern "C" void kernel_launch(void* const* d_in, const int* in_sizes, int n_in,
                              void* d_out, int out_size) {
    // Identify inputs by element count (robust to metadata ordering):
    //   x: n*512 (largest), edge_index: 2*e (second largest),
    //   w1: 8192, w2: 256, b1/b2: 16 each (b1 first in any stable order).
    const float* x = nullptr; const void* ei = nullptr;
    const float* w1 = nullptr; const float* w2 = nullptr;
    const float* b1 = nullptr; const float* b2 = nullptr;
    long long x_sz = 0, e_sz = 0;
    for (int i = 0; i < n_in; i++) {
        long long sz = in_sizes[i];
        if (sz == 16) {
            if (!b1) b1 = (const float*)d_in[i];
            else     b2 = (const float*)d_in[i];
        } else if (sz == 256) {
            w2 = (const float*)d_in[i];
        } else if (sz == 8192) {
            w1 = (const float*)d_in[i];
        } else if (sz > 8192) {
            if (!x) { x = (const float*)d_in[i]; x_sz = sz; }
            else if (sz > x_sz) { ei = (const void*)x; e_sz = x_sz;
                                  x = (const float*)d_in[i]; x_sz = sz; }
            else { ei = (const void*)d_in[i]; e_sz = sz; }
        }
    }

    float* out = (float*)d_out;
    int n = (int)(x_sz / 512);
    int e = (int)(e_sz / 2);
    if (n > N_MAX) n = N_MAX;
    if (e > E_MAX) e = E_MAX;

    int nb = (n + 1023) / 1024;

    k_detect<<<1, 32>>>((const int*)ei, e);
    k_zero_deg<<<(n + 255) / 256, 256>>>(n);
    k_count<<<(e + 255) / 256, 256>>>(ei, e, n);
    k_scan_block<<<nb, 1024>>>(n);
    k_scan_sums<<<1, 32>>>(nb);
    k_scan_add<<<(n + 255) / 256, 256>>>(n, nb);
    k_place<<<(e + 255) / 256, 256>>>(ei, e, n);
    k_gemm1<<<(n + 127) / 128, 128>>>(x, w1, n);
    k_gather1<<<(n * 4 + 255) / 256, 256>>>(b1, w2, n);
    k_gather2<<<(n * 4 + 255) / 256, 256>>>(b2, out, n);
}

// round 5
// speedup vs baseline: 3.4115x; 3.4115x over previous
#include <cuda_runtime.h>
#include <cstdint>

#define N_MAX 100000
#define E_MAX 3200000
#define TK 64

// ---------------- scratch (static device globals; no allocs) ----------------
__device__ int   d_is64;
__device__ int   d_deg[N_MAX];
__device__ int   d_row[N_MAX + 1];
__device__ int   d_pos[N_MAX];
__device__ int   d_bsum[256];
__device__ int   d_srcs[E_MAX];
__device__ float d_dis[N_MAX];
__device__ float d_g1[(size_t)N_MAX * 16];
__device__ float d_g2[(size_t)N_MAX * 16];

// ---------------- dtype probe (parallel): int64 edges have zero high words ----------------
__global__ void k_detect(const int* __restrict__ ei32, int e) {
    __shared__ int s_nz;
    if (threadIdx.x == 0) s_nz = 0;
    __syncthreads();
    int total32 = 2 * e;               // safe bound under BOTH interpretations
    int stride = (total32 / 2048) * 2; // even stride keeps parity odd
    if (stride < 2) stride = 2;
    int nz = 0;
#pragma unroll
    for (int r = 0; r < 4; r++) {
        long long p = 1 + (long long)(threadIdx.x * 4 + r) * stride;
        if (p < total32) nz += (__ldg(&ei32[p]) != 0);
    }
    if (__syncthreads_or(nz)) { if (threadIdx.x == 0) d_is64 = 0; }
    else                      { if (threadIdx.x == 0) d_is64 = 1; }
}

__device__ __forceinline__ int load_idx(const void* ei, long long pos, int is64) {
    return is64 ? (int)((const long long*)ei)[pos] : ((const int*)ei)[pos];
}

// ---------------- degree + counting sort ----------------
__global__ void k_zero_deg(int n) {
    int i = blockIdx.x * blockDim.x + threadIdx.x;
    if (i < n) d_deg[i] = 0;
}

__global__ void k_count(const void* __restrict__ ei, int e, int n) {
    int i = blockIdx.x * blockDim.x + threadIdx.x;
    if (i < e) {
        int is64 = d_is64;
        int d = load_idx(ei, (long long)e + i, is64);   // dst = second row
        if (d >= 0 && d < n) atomicAdd(&d_deg[d], 1);
    }
}

// block-wise exclusive scan of deg into row, block totals into bsum
__global__ void k_scan_block(int n) {
    __shared__ int sh[1024];
    int i = blockIdx.x * 1024 + threadIdx.x;
    int v = (i < n) ? d_deg[i] : 0;
    sh[threadIdx.x] = v;
    __syncthreads();
    for (int off = 1; off < 1024; off <<= 1) {
        int t = (threadIdx.x >= off) ? sh[threadIdx.x - off] : 0;
        __syncthreads();
        sh[threadIdx.x] += t;
        __syncthreads();
    }
    if (i < n) d_row[i] = sh[threadIdx.x] - v;   // exclusive
    if (threadIdx.x == 1023) d_bsum[blockIdx.x] = sh[1023];
}

// parallel scan of block totals (nb <= 128)
__global__ void k_scan_sums(int nb) {
    __shared__ int sh[128];
    int t = threadIdx.x;
    int v = (t < nb) ? d_bsum[t] : 0;
    sh[t] = v;
    __syncthreads();
    for (int off = 1; off < 128; off <<= 1) {
        int u = (t >= off) ? sh[t - off] : 0;
        __syncthreads();
        sh[t] += u;
        __syncthreads();
    }
    if (t < nb) d_bsum[t] = sh[t] - v;       // exclusive
    if (t == nb - 1) d_bsum[nb] = sh[t];     // total
}

__global__ void k_scan_add(int n, int nb) {
    int i = blockIdx.x * blockDim.x + threadIdx.x;
    if (i < n) {
        int r = d_row[i] + d_bsum[i >> 10];
        d_row[i] = r;
        d_pos[i] = r;
        d_dis[i] = rsqrtf((float)(d_deg[i] + 1));   // +1 = self loop
    }
    if (i == 0) d_row[n] = d_bsum[nb];
}

__global__ void k_place(const void* __restrict__ ei, int e, int n) {
    int i = blockIdx.x * blockDim.x + threadIdx.x;
    if (i < e) {
        int is64 = d_is64;
        int s = load_idx(ei, i, is64);                  // src = first row
        int d = load_idx(ei, (long long)e + i, is64);   // dst = second row
        if (d >= 0 && d < n && s >= 0 && s < n) {
            int p = atomicAdd(&d_pos[d], 1);
            if (p >= 0 && p < E_MAX) d_srcs[p] = s;
        }
    }
}

// ---------------- layer-1 GEMM: g1 = (x @ w1) * dis  (packed f32x2 FMA) ----------------
__global__ void __launch_bounds__(128) k_gemm1(const float* __restrict__ x,
                                               const float* __restrict__ w1, int n) {
    __shared__ float xs[TK][129];      // pad 129: reads (k+tid)%32 CF, writes 2-way
    __shared__ float ws[TK * 16];
    int tid = threadIdx.x;
    int node = blockIdx.x * 128 + tid;

    unsigned long long acc[8];
#pragma unroll
    for (int i = 0; i < 8; i++) acc[i] = 0ull;

    for (int kt = 0; kt < 512; kt += TK) {
#pragma unroll
        for (int r = 0; r < 2; r++) {
            int f4 = r * 128 + tid;
            *(float4*)&ws[f4 * 4] = *(const float4*)&w1[kt * 16 + f4 * 4];
        }
#pragma unroll
        for (int r = 0; r < 16; r++) {
            int f4 = r * 128 + tid;          // 0..2047
            int rown = f4 >> 4;              // local node
            int col4 = f4 & 15;              // float4 index within TK
            int gn = blockIdx.x * 128 + rown;
            float4 v = make_float4(0.f, 0.f, 0.f, 0.f);
            if (gn < n) v = *(const float4*)&x[(size_t)gn * 512 + kt + col4 * 4];
            int k0 = col4 * 4;
            xs[k0 + 0][rown] = v.x;
            xs[k0 + 1][rown] = v.y;
            xs[k0 + 2][rown] = v.z;
            xs[k0 + 3][rown] = v.w;
        }
        __syncthreads();
#pragma unroll 8
        for (int k = 0; k < TK; k++) {
            float xv = xs[k][tid];
            unsigned long long xx;
            asm("mov.b64 %0, {%1, %1};" : "=l"(xx) : "f"(xv));
            const unsigned long long* wp = (const unsigned long long*)&ws[k * 16];
#pragma unroll
            for (int q = 0; q < 8; q++)
                asm("fma.rn.f32x2 %0, %1, %2, %0;" : "+l"(acc[q]) : "l"(xx), "l"(wp[q]));
        }
        __syncthreads();
    }

    if (node < n) {
        float di = d_dis[node];
        float outv[16];
#pragma unroll
        for (int q = 0; q < 8; q++) {
            float lo, hi;
            asm("mov.b64 {%0, %1}, %2;" : "=f"(lo), "=f"(hi) : "l"(acc[q]));
            outv[2 * q]     = lo * di;
            outv[2 * q + 1] = hi * di;
        }
#pragma unroll
        for (int q = 0; q < 4; q++)
            *(float4*)&d_g1[(size_t)node * 16 + q * 4] =
                make_float4(outv[4 * q], outv[4 * q + 1], outv[4 * q + 2], outv[4 * q + 3]);
    }
}

// ---------------- gather 1: 8 threads/node (2-way edge split), fused GEMM2 ----------------
__global__ void k_gather1(const float* __restrict__ b1,
                          const float* __restrict__ w2, int n) {
    __shared__ float w2s[256];
    if (threadIdx.x < 256) w2s[threadIdx.x] = w2[threadIdx.x];
    __syncthreads();

    int t = blockIdx.x * blockDim.x + threadIdx.x;
    int node = t >> 3, c = t & 3, h = (t >> 2) & 1;
    bool act = node < n;
    int nc = act ? node : (n - 1);

    int rs = __ldg(&d_row[nc]), re = __ldg(&d_row[nc + 1]);
    float di = __ldg(&d_dis[nc]);
    float4 acc = make_float4(0.f, 0.f, 0.f, 0.f);
    if (h == 0) acc = *(const float4*)&d_g1[(size_t)nc * 16 + c * 4];  // self-loop
    for (int e2 = rs + h; e2 < re; e2 += 2) {
        int s = __ldg(&d_srcs[e2]);
        float4 v = *(const float4*)&d_g1[(size_t)s * 16 + c * 4];
        acc.x += v.x; acc.y += v.y; acc.z += v.z; acc.w += v.w;
    }
    // combine the two halves (lane ±4)
    acc.x += __shfl_xor_sync(0xffffffffu, acc.x, 4);
    acc.y += __shfl_xor_sync(0xffffffffu, acc.y, 4);
    acc.z += __shfl_xor_sync(0xffffffffu, acc.z, 4);
    acc.w += __shfl_xor_sync(0xffffffffu, acc.w, 4);

    float4 b4 = *(const float4*)&b1[c * 4];
    float al[4];
    al[0] = fmaxf(fmaf(acc.x, di, b4.x), 0.f);
    al[1] = fmaxf(fmaf(acc.y, di, b4.y), 0.f);
    al[2] = fmaxf(fmaf(acc.z, di, b4.z), 0.f);
    al[3] = fmaxf(fmaf(acc.w, di, b4.w), 0.f);

    // 16x16 GEMM via shuffle exchange within aligned group of 4 lanes
    int lane = threadIdx.x & 31;
    int lb = lane & ~3;
    float h2[4] = {0.f, 0.f, 0.f, 0.f};
#pragma unroll
    for (int j = 0; j < 16; j++) {
        float aj = __shfl_sync(0xffffffffu, al[j & 3], lb + (j >> 2));
#pragma unroll
        for (int q = 0; q < 4; q++)
            h2[q] = fmaf(aj, w2s[j * 16 + c * 4 + q], h2[q]);
    }
    if (act && h == 0)
        *(float4*)&d_g2[(size_t)node * 16 + c * 4] =
            make_float4(h2[0] * di, h2[1] * di, h2[2] * di, h2[3] * di);
}

// ---------------- gather 2: 8 threads/node, logits + log_softmax ----------------
__global__ void k_gather2(const float* __restrict__ b2, float* __restrict__ out, int n) {
    int t = blockIdx.x * blockDim.x + threadIdx.x;
    int node = t >> 3, c = t & 3, h = (t >> 2) & 1;
    bool act = node < n;
    int nc = act ? node : (n - 1);

    int rs = __ldg(&d_row[nc]), re = __ldg(&d_row[nc + 1]);
    float di = __ldg(&d_dis[nc]);
    float4 acc = make_float4(0.f, 0.f, 0.f, 0.f);
    if (h == 0) acc = *(const float4*)&d_g2[(size_t)nc * 16 + c * 4];  // self-loop
    for (int e2 = rs + h; e2 < re; e2 += 2) {
        int s = __ldg(&d_srcs[e2]);
        float4 v = *(const float4*)&d_g2[(size_t)s * 16 + c * 4];
        acc.x += v.x; acc.y += v.y; acc.z += v.z; acc.w += v.w;
    }
    acc.x += __shfl_xor_sync(0xffffffffu, acc.x, 4);
    acc.y += __shfl_xor_sync(0xffffffffu, acc.y, 4);
    acc.z += __shfl_xor_sync(0xffffffffu, acc.z, 4);
    acc.w += __shfl_xor_sync(0xffffffffu, acc.w, 4);

    float4 b4 = *(const float4*)&b2[c * 4];
    float l0 = fmaf(acc.x, di, b4.x);
    float l1 = fmaf(acc.y, di, b4.y);
    float l2 = fmaf(acc.z, di, b4.z);
    float l3 = fmaf(acc.w, di, b4.w);

    float m = fmaxf(fmaxf(l0, l1), fmaxf(l2, l3));
    m = fmaxf(m, __shfl_xor_sync(0xffffffffu, m, 1));
    m = fmaxf(m, __shfl_xor_sync(0xffffffffu, m, 2));
    float s4 = expf(l0 - m) + expf(l1 - m) + expf(l2 - m) + expf(l3 - m);
    s4 += __shfl_xor_sync(0xffffffffu, s4, 1);
    s4 += __shfl_xor_sync(0xffffffffu, s4, 2);
    float lse = m + logf(s4);

    if (act && h == 0)
        *(float4*)&out[(size_t)node * 16 + c * 4] =
            make_float4(l0 - lse, l1 - lse, l2 - lse, l3 - lse);
}

// ---------------- launch ----------------
extern "C" void kernel_launch(void* const* d_in, const int* in_sizes, int n_in,
                              void* d_out, int out_size) {
    // Identify inputs by element count (robust to metadata ordering).
    const float* x = nullptr; const void* ei = nullptr;
    const float* w1 = nullptr; const float* w2 = nullptr;
    const float* b1 = nullptr; const float* b2 = nullptr;
    long long x_sz = 0, e_sz = 0;
    for (int i = 0; i < n_in; i++) {
        long long sz = in_sizes[i];
        if (sz == 16) {
            if (!b1) b1 = (const float*)d_in[i];
            else     b2 = (const float*)d_in[i];
        } else if (sz == 256) {
            w2 = (const float*)d_in[i];
        } else if (sz == 8192) {
            w1 = (const float*)d_in[i];
        } else if (sz > 8192) {
            if (!x) { x = (const float*)d_in[i]; x_sz = sz; }
            else if (sz > x_sz) { ei = (const void*)x; e_sz = x_sz;
                                  x = (const float*)d_in[i]; x_sz = sz; }
            else { ei = (const void*)d_in[i]; e_sz = sz; }
        }
    }

    float* out = (float*)d_out;
    int n = (int)(x_sz / 512);
    int e = (int)(e_sz / 2);
    if (n > N_MAX) n = N_MAX;
    if (e > E_MAX) e = E_MAX;

    int nb = (n + 1023) / 1024;

    k_detect<<<1, 256>>>((const int*)ei, e);
    k_zero_deg<<<(n + 255) / 256, 256>>>(n);
    k_count<<<(e + 255) / 256, 256>>>(ei, e, n);
    k_scan_block<<<nb, 1024>>>(n);
    k_scan_sums<<<1, 128>>>(nb);
    k_scan_add<<<(n + 255) / 256, 256>>>(n, nb);
    k_place<<<(e + 255) / 256, 256>>>(ei, e, n);
    k_gemm1<<<(n + 127) / 128, 128>>>(x, w1, n);
    k_gather1<<<(n * 8 + 255) / 256, 256>>>(b1, w2, n);
    k_gather2<<<(n * 8 + 255) / 256, 256>>>(b2, out, n);
}

// round 6
// speedup vs baseline: 3.8640x; 1.1326x over previous
#include <cuda_runtime.h>
#include <cstdint>

#define N_MAX 100000
#define E_MAX 3200000

#define G1_NODES 256
#define G1_TK 32
#define G1_PAD 36

// ---------------- scratch (static device globals; no allocs) ----------------
__device__ int   d_is64;
__device__ int   d_deg[N_MAX];
__device__ int   d_row[N_MAX + 1];
__device__ int   d_pos[N_MAX];
__device__ int   d_bsum[256];
__device__ int   d_srcs[E_MAX];
__device__ float d_dis[N_MAX];
__device__ float d_g1[(size_t)N_MAX * 16];
__device__ float d_g2[(size_t)N_MAX * 16];

// ---------------- init: zero degrees; block 0 also probes edge dtype ----------------
__global__ void k_init(const int* __restrict__ ei32, int e, int n) {
    int i = blockIdx.x * blockDim.x + threadIdx.x;
    if (i < n) d_deg[i] = 0;
    if (blockIdx.x == 0) {
        // int64 little-endian node ids < 2^31 have zero high words at odd int32 offsets
        int total32 = 2 * e;               // in-bounds under BOTH interpretations
        int stride = (total32 / 2048) * 2; // even stride keeps parity odd
        if (stride < 2) stride = 2;
        int nz = 0;
#pragma unroll
        for (int r = 0; r < 4; r++) {
            long long p = 1 + (long long)(threadIdx.x * 4 + r) * stride;
            if (p < total32) nz += (__ldg(&ei32[p]) != 0);
        }
        int any = __syncthreads_or(nz);
        if (threadIdx.x == 0) d_is64 = any ? 0 : 1;
    }
}

__device__ __forceinline__ int load_idx(const void* ei, long long pos, int is64) {
    return is64 ? (int)((const long long*)ei)[pos] : ((const int*)ei)[pos];
}

__global__ void k_count(const void* __restrict__ ei, int e, int n) {
    int i = blockIdx.x * blockDim.x + threadIdx.x;
    if (i < e) {
        int is64 = d_is64;
        int d = load_idx(ei, (long long)e + i, is64);   // dst = second row
        if (d >= 0 && d < n) atomicAdd(&d_deg[d], 1);
    }
}

// block-wise exclusive scan of deg into row, raw block totals into bsum
__global__ void k_scan_block(int n) {
    __shared__ int sh[1024];
    int i = blockIdx.x * 1024 + threadIdx.x;
    int v = (i < n) ? d_deg[i] : 0;
    sh[threadIdx.x] = v;
    __syncthreads();
    for (int off = 1; off < 1024; off <<= 1) {
        int t = (threadIdx.x >= off) ? sh[threadIdx.x - off] : 0;
        __syncthreads();
        sh[threadIdx.x] += t;
        __syncthreads();
    }
    if (i < n) d_row[i] = sh[threadIdx.x] - v;   // exclusive within block
    if (threadIdx.x == 1023) d_bsum[blockIdx.x] = sh[1023];
}

// add block-prefix (computed redundantly per block), build pos/dis
__global__ void k_scan_add(int n, int nb) {
    __shared__ int sh[256];
    int tid = threadIdx.x;
    int i = blockIdx.x * 256 + tid;
    int seg = blockIdx.x >> 2;                 // 256-thread block sits in one 1024-segment
    int v = (tid < nb) ? d_bsum[tid] : 0;

    sh[tid] = (tid < seg) ? v : 0;             // prefix over earlier segments
    __syncthreads();
    for (int off = 128; off >= 1; off >>= 1) {
        if (tid < off) sh[tid] += sh[tid + off];
        __syncthreads();
    }
    int S = sh[0];
    __syncthreads();
    sh[tid] = v;                               // total over all segments
    __syncthreads();
    for (int off = 128; off >= 1; off >>= 1) {
        if (tid < off) sh[tid] += sh[tid + off];
        __syncthreads();
    }
    int total = sh[0];

    if (i < n) {
        int r = d_row[i] + S;
        d_row[i] = r;
        d_pos[i] = r;
        d_dis[i] = rsqrtf((float)(d_deg[i] + 1));   // +1 = self loop
    }
    if (i == 0) d_row[n] = total;
}

__global__ void k_place(const void* __restrict__ ei, int e, int n) {
    int i = blockIdx.x * blockDim.x + threadIdx.x;
    if (i < e) {
        int is64 = d_is64;
        int s = load_idx(ei, i, is64);                  // src = first row
        int d = load_idx(ei, (long long)e + i, is64);   // dst = second row
        if (d >= 0 && d < n && s >= 0 && s < n) {
            int p = atomicAdd(&d_pos[d], 1);
            if (p >= 0 && p < E_MAX) d_srcs[p] = s;
        }
    }
}

// ---------------- layer-1 GEMM: g1 = (x @ w1) * dis ----------------
// 2 nodes/thread, float4 smem traffic, packed f32x2 FMA.
__global__ void __launch_bounds__(128) k_gemm1(const float* __restrict__ x,
                                               const float* __restrict__ w1, int n) {
    __shared__ float xs[G1_NODES][G1_PAD];   // 36 KB: row-major, pad 36 (CF float4 reads)
    __shared__ float ws[G1_TK * 16];         // 2 KB
    int tid = threadIdx.x;
    int base = blockIdx.x * G1_NODES;

    unsigned long long a0[8], a1[8];
#pragma unroll
    for (int q = 0; q < 8; q++) { a0[q] = 0ull; a1[q] = 0ull; }

    for (int kt = 0; kt < 512; kt += G1_TK) {
        // w tile: 32*16 floats = 128 float4, one per thread
        ((float4*)ws)[tid] = ((const float4*)(w1 + (size_t)kt * 16))[tid];
        // x tile: 256 rows x 8 float4 = 2048 float4, 16 per thread (coalesced)
#pragma unroll
        for (int r = 0; r < 16; r++) {
            int f4 = r * 128 + tid;
            int rown = f4 >> 3;              // 0..255
            int col  = f4 & 7;               // 0..7
            int gn = base + rown;
            float4 v = make_float4(0.f, 0.f, 0.f, 0.f);
            if (gn < n) v = *(const float4*)&x[(size_t)gn * 512 + kt + col * 4];
            *(float4*)&xs[rown][col * 4] = v;
        }
        __syncthreads();
#pragma unroll
        for (int k4 = 0; k4 < G1_TK / 4; k4++) {
            float4 xa = *(const float4*)&xs[tid][k4 * 4];
            float4 xb = *(const float4*)&xs[tid + 128][k4 * 4];
#pragma unroll
            for (int kk = 0; kk < 4; kk++) {
                int k = k4 * 4 + kk;
                const ulonglong2* wp2 = (const ulonglong2*)&ws[k * 16];
                float fa = (&xa.x)[kk];
                float fb = (&xb.x)[kk];
                unsigned long long pa, pb;
                asm("mov.b64 %0, {%1, %1};" : "=l"(pa) : "f"(fa));
                asm("mov.b64 %0, {%1, %1};" : "=l"(pb) : "f"(fb));
#pragma unroll
                for (int q = 0; q < 4; q++) {
                    ulonglong2 w2v = wp2[q];
                    asm("fma.rn.f32x2 %0, %1, %2, %0;" : "+l"(a0[2 * q])     : "l"(pa), "l"(w2v.x));
                    asm("fma.rn.f32x2 %0, %1, %2, %0;" : "+l"(a0[2 * q + 1]) : "l"(pa), "l"(w2v.y));
                    asm("fma.rn.f32x2 %0, %1, %2, %0;" : "+l"(a1[2 * q])     : "l"(pb), "l"(w2v.x));
                    asm("fma.rn.f32x2 %0, %1, %2, %0;" : "+l"(a1[2 * q + 1]) : "l"(pb), "l"(w2v.y));
                }
            }
        }
        __syncthreads();
    }

#pragma unroll
    for (int half = 0; half < 2; half++) {
        int node = base + half * 128 + tid;
        if (node < n) {
            unsigned long long* ap = half ? a1 : a0;
            float di = __ldg(&d_dis[node]);
            float outv[16];
#pragma unroll
            for (int q = 0; q < 8; q++) {
                float lo, hi;
                asm("mov.b64 {%0, %1}, %2;" : "=f"(lo), "=f"(hi) : "l"(ap[q]));
                outv[2 * q]     = lo * di;
                outv[2 * q + 1] = hi * di;
            }
#pragma unroll
            for (int q = 0; q < 4; q++)
                *(float4*)&d_g1[(size_t)node * 16 + q * 4] =
                    make_float4(outv[4 * q], outv[4 * q + 1], outv[4 * q + 2], outv[4 * q + 3]);
        }
    }
}

// ---------------- gather 1: 8 threads/node (2-way edge split), fused GEMM2 ----------------
__global__ void k_gather1(const float* __restrict__ b1,
                          const float* __restrict__ w2, int n) {
    __shared__ float w2s[256];
    if (threadIdx.x < 256) w2s[threadIdx.x] = w2[threadIdx.x];
    __syncthreads();

    int t = blockIdx.x * blockDim.x + threadIdx.x;
    int node = t >> 3, c = t & 3, h = (t >> 2) & 1;
    bool act = node < n;
    int nc = act ? node : (n - 1);

    int rs = __ldg(&d_row[nc]), re = __ldg(&d_row[nc + 1]);
    float di = __ldg(&d_dis[nc]);
    float4 acc = make_float4(0.f, 0.f, 0.f, 0.f);
    if (h == 0) acc = *(const float4*)&d_g1[(size_t)nc * 16 + c * 4];  // self-loop
#pragma unroll 4
    for (int e2 = rs + h; e2 < re; e2 += 2) {
        int s = __ldg(&d_srcs[e2]);
        float4 v = *(const float4*)&d_g1[(size_t)s * 16 + c * 4];
        acc.x += v.x; acc.y += v.y; acc.z += v.z; acc.w += v.w;
    }
    acc.x += __shfl_xor_sync(0xffffffffu, acc.x, 4);
    acc.y += __shfl_xor_sync(0xffffffffu, acc.y, 4);
    acc.z += __shfl_xor_sync(0xffffffffu, acc.z, 4);
    acc.w += __shfl_xor_sync(0xffffffffu, acc.w, 4);

    float4 b4 = *(const float4*)&b1[c * 4];
    float al[4];
    al[0] = fmaxf(fmaf(acc.x, di, b4.x), 0.f);
    al[1] = fmaxf(fmaf(acc.y, di, b4.y), 0.f);
    al[2] = fmaxf(fmaf(acc.z, di, b4.z), 0.f);
    al[3] = fmaxf(fmaf(acc.w, di, b4.w), 0.f);

    int lane = threadIdx.x & 31;
    int lb = lane & ~3;
    float h2[4] = {0.f, 0.f, 0.f, 0.f};
#pragma unroll
    for (int j = 0; j < 16; j++) {
        float aj = __shfl_sync(0xffffffffu, al[j & 3], lb + (j >> 2));
#pragma unroll
        for (int q = 0; q < 4; q++)
            h2[q] = fmaf(aj, w2s[j * 16 + c * 4 + q], h2[q]);
    }
    if (act && h == 0)
        *(float4*)&d_g2[(size_t)node * 16 + c * 4] =
            make_float4(h2[0] * di, h2[1] * di, h2[2] * di, h2[3] * di);
}

// ---------------- gather 2: 8 threads/node, logits + log_softmax ----------------
__global__ void k_gather2(const float* __restrict__ b2, float* __restrict__ out, int n) {
    int t = blockIdx.x * blockDim.x + threadIdx.x;
    int node = t >> 3, c = t & 3, h = (t >> 2) & 1;
    bool act = node < n;
    int nc = act ? node : (n - 1);

    int rs = __ldg(&d_row[nc]), re = __ldg(&d_row[nc + 1]);
    float di = __ldg(&d_dis[nc]);
    float4 acc = make_float4(0.f, 0.f, 0.f, 0.f);
    if (h == 0) acc = *(const float4*)&d_g2[(size_t)nc * 16 + c * 4];  // self-loop
#pragma unroll 4
    for (int e2 = rs + h; e2 < re; e2 += 2) {
        int s = __ldg(&d_srcs[e2]);
        float4 v = *(const float4*)&d_g2[(size_t)s * 16 + c * 4];
        acc.x += v.x; acc.y += v.y; acc.z += v.z; acc.w += v.w;
    }
    acc.x += __shfl_xor_sync(0xffffffffu, acc.x, 4);
    acc.y += __shfl_xor_sync(0xffffffffu, acc.y, 4);
    acc.z += __shfl_xor_sync(0xffffffffu, acc.z, 4);
    acc.w += __shfl_xor_sync(0xffffffffu, acc.w, 4);

    float4 b4 = *(const float4*)&b2[c * 4];
    float l0 = fmaf(acc.x, di, b4.x);
    float l1 = fmaf(acc.y, di, b4.y);
    float l2 = fmaf(acc.z, di, b4.z);
    float l3 = fmaf(acc.w, di, b4.w);

    float m = fmaxf(fmaxf(l0, l1), fmaxf(l2, l3));
    m = fmaxf(m, __shfl_xor_sync(0xffffffffu, m, 1));
    m = fmaxf(m, __shfl_xor_sync(0xffffffffu, m, 2));
    float s4 = expf(l0 - m) + expf(l1 - m) + expf(l2 - m) + expf(l3 - m);
    s4 += __shfl_xor_sync(0xffffffffu, s4, 1);
    s4 += __shfl_xor_sync(0xffffffffu, s4, 2);
    float lse = m + logf(s4);

    if (act && h == 0)
        *(float4*)&out[(size_t)node * 16 + c * 4] =
            make_float4(l0 - lse, l1 - lse, l2 - lse, l3 - lse);
}

// ---------------- launch ----------------
extern "C" void kernel_launch(void* const* d_in, const int* in_sizes, int n_in,
                              void* d_out, int out_size) {
    // Identify inputs by element count (robust to metadata ordering).
    const float* x = nullptr; const void* ei = nullptr;
    const float* w1 = nullptr; const float* w2 = nullptr;
    const float* b1 = nullptr; const float* b2 = nullptr;
    long long x_sz = 0, e_sz = 0;
    for (int i = 0; i < n_in; i++) {
        long long sz = in_sizes[i];
        if (sz == 16) {
            if (!b1) b1 = (const float*)d_in[i];
            else     b2 = (const float*)d_in[i];
        } else if (sz == 256) {
            w2 = (const float*)d_in[i];
        } else if (sz == 8192) {
            w1 = (const float*)d_in[i];
        } else if (sz > 8192) {
            if (!x) { x = (const float*)d_in[i]; x_sz = sz; }
            else if (sz > x_sz) { ei = (const void*)x; e_sz = x_sz;
                                  x = (const float*)d_in[i]; x_sz = sz; }
            else { ei = (const void*)d_in[i]; e_sz = sz; }
        }
    }

    float* out = (float*)d_out;
    int n = (int)(x_sz / 512);
    int e = (int)(e_sz / 2);
    if (n > N_MAX) n = N_MAX;
    if (e > E_MAX) e = E_MAX;

    int nb = (n + 1023) / 1024;

    k_init<<<(n + 255) / 256, 256>>>((const int*)ei, e, n);          // 1
    k_count<<<(e + 255) / 256, 256>>>(ei, e, n);                     // 2
    k_scan_block<<<nb, 1024>>>(n);                                   // 3
    k_scan_add<<<(n + 255) / 256, 256>>>(n, nb);                     // 4
    k_place<<<(e + 255) / 256, 256>>>(ei, e, n);                     // 5
    k_gemm1<<<(n + G1_NODES - 1) / G1_NODES, 128>>>(x, w1, n);       // 6  <- ncu -s 5
    k_gather1<<<(n * 8 + 255) / 256, 256>>>(b1, w2, n);              // 7
    k_gather2<<<(n * 8 + 255) / 256, 256>>>(b2, out, n);             // 8
}

// round 7
// speedup vs baseline: 4.5758x; 1.1842x over previous
#include <cuda_runtime.h>
#include <cstdint>

#define N_MAX 100000
#define E_MAX 3200000

#define G1_NODES 256
#define G1_TK 32
#define G1_PAD 36

// ---------------- scratch (static device globals; no allocs) ----------------
__device__ int   d_is64;
__device__ int   d_deg[N_MAX];
__device__ int   d_row[N_MAX + 1];
__device__ int   d_pos[N_MAX];
__device__ int   d_bsum[256];
__device__ int   d_srcs[E_MAX];
__device__ float d_dis[N_MAX];
__device__ float d_g1[(size_t)N_MAX * 16];
__device__ float d_g2[(size_t)N_MAX * 16];

// ---------------- init: zero degrees; block 0 also probes edge dtype ----------------
__global__ void k_init(const int* __restrict__ ei32, int e, int n) {
    int i = blockIdx.x * blockDim.x + threadIdx.x;
    if (i < n) d_deg[i] = 0;
    if (blockIdx.x == 0) {
        // int64 little-endian node ids < 2^31 have zero high words at odd int32 offsets
        int total32 = 2 * e;               // in-bounds under BOTH interpretations
        int stride = (total32 / 2048) * 2; // even stride keeps parity odd
        if (stride < 2) stride = 2;
        int nz = 0;
#pragma unroll
        for (int r = 0; r < 4; r++) {
            long long p = 1 + (long long)(threadIdx.x * 4 + r) * stride;
            if (p < total32) nz += (__ldg(&ei32[p]) != 0);
        }
        int any = __syncthreads_or(nz);
        if (threadIdx.x == 0) d_is64 = any ? 0 : 1;
    }
}

__device__ __forceinline__ int load_idx(const void* ei, long long pos, int is64) {
    return is64 ? (int)((const long long*)ei)[pos] : ((const int*)ei)[pos];
}

__global__ void k_count(const void* __restrict__ ei, int e, int n) {
    int i = blockIdx.x * blockDim.x + threadIdx.x;
    if (i < e) {
        int is64 = d_is64;
        int d = load_idx(ei, (long long)e + i, is64);   // dst = second row
        if (d >= 0 && d < n) atomicAdd(&d_deg[d], 1);
    }
}

// block-wise exclusive scan of deg into row, raw block totals into bsum
__global__ void k_scan_block(int n) {
    __shared__ int sh[1024];
    int i = blockIdx.x * 1024 + threadIdx.x;
    int v = (i < n) ? d_deg[i] : 0;
    sh[threadIdx.x] = v;
    __syncthreads();
    for (int off = 1; off < 1024; off <<= 1) {
        int t = (threadIdx.x >= off) ? sh[threadIdx.x - off] : 0;
        __syncthreads();
        sh[threadIdx.x] += t;
        __syncthreads();
    }
    if (i < n) d_row[i] = sh[threadIdx.x] - v;   // exclusive within block
    if (threadIdx.x == 1023) d_bsum[blockIdx.x] = sh[1023];
}

// add block-prefix (computed redundantly per block), build pos/dis
__global__ void k_scan_add(int n, int nb) {
    __shared__ int sh[256];
    int tid = threadIdx.x;
    int i = blockIdx.x * 256 + tid;
    int seg = blockIdx.x >> 2;                 // 256-thread block sits in one 1024-segment
    int v = (tid < nb) ? d_bsum[tid] : 0;

    sh[tid] = (tid < seg) ? v : 0;             // prefix over earlier segments
    __syncthreads();
    for (int off = 128; off >= 1; off >>= 1) {
        if (tid < off) sh[tid] += sh[tid + off];
        __syncthreads();
    }
    int S = sh[0];
    __syncthreads();
    sh[tid] = v;                               // total over all segments
    __syncthreads();
    for (int off = 128; off >= 1; off >>= 1) {
        if (tid < off) sh[tid] += sh[tid + off];
        __syncthreads();
    }
    int total = sh[0];

    if (i < n) {
        int r = d_row[i] + S;
        d_row[i] = r;
        d_pos[i] = r;
        d_dis[i] = rsqrtf((float)(d_deg[i] + 1));   // +1 = self loop
    }
    if (i == 0) d_row[n] = total;
}

__global__ void k_place(const void* __restrict__ ei, int e, int n) {
    int i = blockIdx.x * blockDim.x + threadIdx.x;
    if (i < e) {
        int is64 = d_is64;
        int s = load_idx(ei, i, is64);                  // src = first row
        int d = load_idx(ei, (long long)e + i, is64);   // dst = second row
        if (d >= 0 && d < n && s >= 0 && s < n) {
            int p = atomicAdd(&d_pos[d], 1);
            if (p >= 0 && p < E_MAX) d_srcs[p] = s;
        }
    }
}

// ---------------- layer-1 GEMM: g1 = x @ w1 (UNscaled; dis applied later) ----------------
// Runs on a forked stream concurrently with graph preprocessing.
__global__ void __launch_bounds__(128) k_gemm1(const float* __restrict__ x,
                                               const float* __restrict__ w1, int n) {
    __shared__ float xs[G1_NODES][G1_PAD];   // 36 KB: row-major, pad 36 (CF float4 reads)
    __shared__ float ws[G1_TK * 16];         // 2 KB
    int tid = threadIdx.x;
    int base = blockIdx.x * G1_NODES;

    unsigned long long a0[8], a1[8];
#pragma unroll
    for (int q = 0; q < 8; q++) { a0[q] = 0ull; a1[q] = 0ull; }

    for (int kt = 0; kt < 512; kt += G1_TK) {
        ((float4*)ws)[tid] = ((const float4*)(w1 + (size_t)kt * 16))[tid];
#pragma unroll
        for (int r = 0; r < 16; r++) {
            int f4 = r * 128 + tid;
            int rown = f4 >> 3;              // 0..255
            int col  = f4 & 7;               // 0..7
            int gn = base + rown;
            float4 v = make_float4(0.f, 0.f, 0.f, 0.f);
            if (gn < n) v = *(const float4*)&x[(size_t)gn * 512 + kt + col * 4];
            *(float4*)&xs[rown][col * 4] = v;
        }
        __syncthreads();
#pragma unroll
        for (int k4 = 0; k4 < G1_TK / 4; k4++) {
            float4 xa = *(const float4*)&xs[tid][k4 * 4];
            float4 xb = *(const float4*)&xs[tid + 128][k4 * 4];
#pragma unroll
            for (int kk = 0; kk < 4; kk++) {
                int k = k4 * 4 + kk;
                const ulonglong2* wp2 = (const ulonglong2*)&ws[k * 16];
                float fa = (&xa.x)[kk];
                float fb = (&xb.x)[kk];
                unsigned long long pa, pb;
                asm("mov.b64 %0, {%1, %1};" : "=l"(pa) : "f"(fa));
                asm("mov.b64 %0, {%1, %1};" : "=l"(pb) : "f"(fb));
#pragma unroll
                for (int q = 0; q < 4; q++) {
                    ulonglong2 w2v = wp2[q];
                    asm("fma.rn.f32x2 %0, %1, %2, %0;" : "+l"(a0[2 * q])     : "l"(pa), "l"(w2v.x));
                    asm("fma.rn.f32x2 %0, %1, %2, %0;" : "+l"(a0[2 * q + 1]) : "l"(pa), "l"(w2v.y));
                    asm("fma.rn.f32x2 %0, %1, %2, %0;" : "+l"(a1[2 * q])     : "l"(pb), "l"(w2v.x));
                    asm("fma.rn.f32x2 %0, %1, %2, %0;" : "+l"(a1[2 * q + 1]) : "l"(pb), "l"(w2v.y));
                }
            }
        }
        __syncthreads();
    }

#pragma unroll
    for (int half = 0; half < 2; half++) {
        int node = base + half * 128 + tid;
        if (node < n) {
            unsigned long long* ap = half ? a1 : a0;
            float outv[16];
#pragma unroll
            for (int q = 0; q < 8; q++) {
                float lo, hi;
                asm("mov.b64 {%0, %1}, %2;" : "=f"(lo), "=f"(hi) : "l"(ap[q]));
                outv[2 * q]     = lo;
                outv[2 * q + 1] = hi;
            }
#pragma unroll
            for (int q = 0; q < 4; q++)
                *(float4*)&d_g1[(size_t)node * 16 + q * 4] =
                    make_float4(outv[4 * q], outv[4 * q + 1], outv[4 * q + 2], outv[4 * q + 3]);
        }
    }
}

// ---------------- scale: g1 *= dis[node] (after join) ----------------
__global__ void k_scale(int n) {
    int t = blockIdx.x * blockDim.x + threadIdx.x;   // one float4 per thread
    int node = t >> 2;
    if (node < n) {
        float di = __ldg(&d_dis[node]);
        float4 v = *(const float4*)&d_g1[(size_t)t * 4];
        v.x *= di; v.y *= di; v.z *= di; v.w *= di;
        *(float4*)&d_g1[(size_t)t * 4] = v;
    }
}

// ---------------- gather 1: 8 threads/node (2-way edge split), fused GEMM2 ----------------
__global__ void k_gather1(const float* __restrict__ b1,
                          const float* __restrict__ w2, int n) {
    __shared__ float w2s[256];
    if (threadIdx.x < 256) w2s[threadIdx.x] = w2[threadIdx.x];
    __syncthreads();

    int t = blockIdx.x * blockDim.x + threadIdx.x;
    int node = t >> 3, c = t & 3, h = (t >> 2) & 1;
    bool act = node < n;
    int nc = act ? node : (n - 1);

    int rs = __ldg(&d_row[nc]), re = __ldg(&d_row[nc + 1]);
    float di = __ldg(&d_dis[nc]);
    float4 acc = make_float4(0.f, 0.f, 0.f, 0.f);
    if (h == 0) acc = *(const float4*)&d_g1[(size_t)nc * 16 + c * 4];  // self-loop
#pragma unroll 4
    for (int e2 = rs + h; e2 < re; e2 += 2) {
        int s = __ldg(&d_srcs[e2]);
        float4 v = *(const float4*)&d_g1[(size_t)s * 16 + c * 4];
        acc.x += v.x; acc.y += v.y; acc.z += v.z; acc.w += v.w;
    }
    acc.x += __shfl_xor_sync(0xffffffffu, acc.x, 4);
    acc.y += __shfl_xor_sync(0xffffffffu, acc.y, 4);
    acc.z += __shfl_xor_sync(0xffffffffu, acc.z, 4);
    acc.w += __shfl_xor_sync(0xffffffffu, acc.w, 4);

    float4 b4 = *(const float4*)&b1[c * 4];
    float al[4];
    al[0] = fmaxf(fmaf(acc.x, di, b4.x), 0.f);
    al[1] = fmaxf(fmaf(acc.y, di, b4.y), 0.f);
    al[2] = fmaxf(fmaf(acc.z, di, b4.z), 0.f);
    al[3] = fmaxf(fmaf(acc.w, di, b4.w), 0.f);

    int lane = threadIdx.x & 31;
    int lb = lane & ~3;
    float h2[4] = {0.f, 0.f, 0.f, 0.f};
#pragma unroll
    for (int j = 0; j < 16; j++) {
        float aj = __shfl_sync(0xffffffffu, al[j & 3], lb + (j >> 2));
#pragma unroll
        for (int q = 0; q < 4; q++)
            h2[q] = fmaf(aj, w2s[j * 16 + c * 4 + q], h2[q]);
    }
    if (act && h == 0)
        *(float4*)&d_g2[(size_t)node * 16 + c * 4] =
            make_float4(h2[0] * di, h2[1] * di, h2[2] * di, h2[3] * di);
}

// ---------------- gather 2: 8 threads/node, logits + log_softmax ----------------
__global__ void k_gather2(const float* __restrict__ b2, float* __restrict__ out, int n) {
    int t = blockIdx.x * blockDim.x + threadIdx.x;
    int node = t >> 3, c = t & 3, h = (t >> 2) & 1;
    bool act = node < n;
    int nc = act ? node : (n - 1);

    int rs = __ldg(&d_row[nc]), re = __ldg(&d_row[nc + 1]);
    float di = __ldg(&d_dis[nc]);
    float4 acc = make_float4(0.f, 0.f, 0.f, 0.f);
    if (h == 0) acc = *(const float4*)&d_g2[(size_t)nc * 16 + c * 4];  // self-loop
#pragma unroll 4
    for (int e2 = rs + h; e2 < re; e2 += 2) {
        int s = __ldg(&d_srcs[e2]);
        float4 v = *(const float4*)&d_g2[(size_t)s * 16 + c * 4];
        acc.x += v.x; acc.y += v.y; acc.z += v.z; acc.w += v.w;
    }
    acc.x += __shfl_xor_sync(0xffffffffu, acc.x, 4);
    acc.y += __shfl_xor_sync(0xffffffffu, acc.y, 4);
    acc.z += __shfl_xor_sync(0xffffffffu, acc.z, 4);
    acc.w += __shfl_xor_sync(0xffffffffu, acc.w, 4);

    float4 b4 = *(const float4*)&b2[c * 4];
    float l0 = fmaf(acc.x, di, b4.x);
    float l1 = fmaf(acc.y, di, b4.y);
    float l2 = fmaf(acc.z, di, b4.z);
    float l3 = fmaf(acc.w, di, b4.w);

    float m = fmaxf(fmaxf(l0, l1), fmaxf(l2, l3));
    m = fmaxf(m, __shfl_xor_sync(0xffffffffu, m, 1));
    m = fmaxf(m, __shfl_xor_sync(0xffffffffu, m, 2));
    float s4 = expf(l0 - m) + expf(l1 - m) + expf(l2 - m) + expf(l3 - m);
    s4 += __shfl_xor_sync(0xffffffffu, s4, 1);
    s4 += __shfl_xor_sync(0xffffffffu, s4, 2);
    float lse = m + logf(s4);

    if (act && h == 0)
        *(float4*)&out[(size_t)node * 16 + c * 4] =
            make_float4(l0 - lse, l1 - lse, l2 - lse, l3 - lse);
}

// ---------------- launch (fork: gemm1 parallel with graph preprocessing) ----------------
extern "C" void kernel_launch(void* const* d_in, const int* in_sizes, int n_in,
                              void* d_out, int out_size) {
    // One-time handles (created on the first, uncaptured, correctness call).
    static cudaStream_t s2 = nullptr;
    static cudaEvent_t ev_fork = nullptr, ev_join = nullptr;
    if (s2 == nullptr) {
        cudaStreamCreateWithFlags(&s2, cudaStreamNonBlocking);
        cudaEventCreateWithFlags(&ev_fork, cudaEventDisableTiming);
        cudaEventCreateWithFlags(&ev_join, cudaEventDisableTiming);
    }

    // Identify inputs by element count (robust to metadata ordering).
    const float* x = nullptr; const void* ei = nullptr;
    const float* w1 = nullptr; const float* w2 = nullptr;
    const float* b1 = nullptr; const float* b2 = nullptr;
    long long x_sz = 0, e_sz = 0;
    for (int i = 0; i < n_in; i++) {
        long long sz = in_sizes[i];
        if (sz == 16) {
            if (!b1) b1 = (const float*)d_in[i];
            else     b2 = (const float*)d_in[i];
        } else if (sz == 256) {
            w2 = (const float*)d_in[i];
        } else if (sz == 8192) {
            w1 = (const float*)d_in[i];
        } else if (sz > 8192) {
            if (!x) { x = (const float*)d_in[i]; x_sz = sz; }
            else if (sz > x_sz) { ei = (const void*)x; e_sz = x_sz;
                                  x = (const float*)d_in[i]; x_sz = sz; }
            else { ei = (const void*)d_in[i]; e_sz = sz; }
        }
    }

    float* out = (float*)d_out;
    int n = (int)(x_sz / 512);
    int e = (int)(e_sz / 2);
    if (n > N_MAX) n = N_MAX;
    if (e > E_MAX) e = E_MAX;

    int nb = (n + 1023) / 1024;

    // fork: gemm1 (independent of graph structure) on s2
    cudaEventRecord(ev_fork, 0);
    cudaStreamWaitEvent(s2, ev_fork, 0);
    k_gemm1<<<(n + G1_NODES - 1) / G1_NODES, 128, 0, s2>>>(x, w1, n);

    // preprocessing chain on the capture (default) stream
    k_init<<<(n + 255) / 256, 256>>>((const int*)ei, e, n);
    k_count<<<(e + 255) / 256, 256>>>(ei, e, n);
    k_scan_block<<<nb, 1024>>>(n);
    k_scan_add<<<(n + 255) / 256, 256>>>(n, nb);
    k_place<<<(e + 255) / 256, 256>>>(ei, e, n);

    // join
    cudaEventRecord(ev_join, s2);
    cudaStreamWaitEvent(0, ev_join, 0);

    k_scale<<<(n * 4 + 255) / 256, 256>>>(n);
    k_gather1<<<(n * 8 + 255) / 256, 256>>>(b1, w2, n);
    k_gather2<<<(n * 8 + 255) / 256, 256>>>(b2, out, n);
}

// round 9
// speedup vs baseline: 4.9893x; 1.0904x over previous
#include <cuda_runtime.h>
#include <cuda_fp16.h>
#include <cstdint>

#define N_MAX 100000
#define E_MAX 3200000

#define G1_NODES 256
#define G1_TK 32
#define G1_PAD 36

// ---------------- scratch (static device globals; no allocs) ----------------
__device__ int    d_is64;
__device__ int    d_deg[N_MAX];
__device__ int    d_row[N_MAX + 1];
__device__ int    d_pos[N_MAX];
__device__ int    d_bsum[256];
__device__ int    d_srcs[E_MAX];
__device__ float  d_dis[N_MAX];
__device__ float  d_g1[(size_t)N_MAX * 16];      // fp32 gemm1 output (unscaled)
__device__ __half d_g1h[(size_t)N_MAX * 16];     // fp16 scaled layer-1 features
__device__ __half d_g2h[(size_t)N_MAX * 16];     // fp16 scaled layer-2 features

// ---------------- init: zero degrees; block 0 also probes edge dtype ----------------
__global__ void k_init(const int* __restrict__ ei32, int e, int n) {
    int i = blockIdx.x * blockDim.x + threadIdx.x;
    if (i < n) d_deg[i] = 0;
    if (blockIdx.x == 0) {
        // int64 little-endian node ids < 2^31 have zero high words at odd int32 offsets
        int total32 = 2 * e;               // in-bounds under BOTH interpretations
        int stride = (total32 / 2048) * 2; // even stride keeps parity odd
        if (stride < 2) stride = 2;
        int nz = 0;
#pragma unroll
        for (int r = 0; r < 4; r++) {
            long long p = 1 + (long long)(threadIdx.x * 4 + r) * stride;
            if (p < total32) nz += (__ldg(&ei32[p]) != 0);
        }
        int any = __syncthreads_or(nz);
        if (threadIdx.x == 0) d_is64 = any ? 0 : 1;
    }
}

__device__ __forceinline__ int load_idx(const void* ei, long long pos, int is64) {
    return is64 ? (int)((const long long*)ei)[pos] : ((const int*)ei)[pos];
}

__global__ void k_count(const void* __restrict__ ei, int e, int n) {
    int i = blockIdx.x * blockDim.x + threadIdx.x;
    if (i < e) {
        int is64 = d_is64;
        int d = load_idx(ei, (long long)e + i, is64);   // dst = second row
        if (d >= 0 && d < n) atomicAdd(&d_deg[d], 1);
    }
}

// block-wise exclusive scan of deg into row (warp-shuffle), block totals into bsum
__global__ void k_scan_block(int n) {
    __shared__ int wsum[32];
    int lane = threadIdx.x & 31, wid = threadIdx.x >> 5;
    int i = blockIdx.x * 1024 + threadIdx.x;
    int v = (i < n) ? d_deg[i] : 0;
    int incl = v;
#pragma unroll
    for (int off = 1; off < 32; off <<= 1) {
        int t = __shfl_up_sync(0xffffffffu, incl, off);
        if (lane >= off) incl += t;
    }
    if (lane == 31) wsum[wid] = incl;
    __syncthreads();
    if (wid == 0) {
        int w = wsum[lane];
#pragma unroll
        for (int off = 1; off < 32; off <<= 1) {
            int t = __shfl_up_sync(0xffffffffu, w, off);
            if (lane >= off) w += t;
        }
        wsum[lane] = w;
    }
    __syncthreads();
    int add = wid ? wsum[wid - 1] : 0;
    incl += add;
    if (i < n) d_row[i] = incl - v;              // exclusive within block
    if (threadIdx.x == 1023) d_bsum[blockIdx.x] = incl;
}

// add block-prefix (single-warp shfl reduction per block), build pos/dis
__global__ void k_scan_add(int n, int nb) {
    __shared__ int sS, sT;
    int tid = threadIdx.x;
    int i = blockIdx.x * 256 + tid;
    int seg = blockIdx.x >> 2;                   // this block's 1024-wide segment
    if (tid < 32) {
        int s_lt = 0, s_all = 0;
        for (int j = tid; j < nb; j += 32) {
            int b = d_bsum[j];
            s_all += b;
            if (j < seg) s_lt += b;
        }
#pragma unroll
        for (int off = 16; off >= 1; off >>= 1) {
            s_lt  += __shfl_xor_sync(0xffffffffu, s_lt, off);
            s_all += __shfl_xor_sync(0xffffffffu, s_all, off);
        }
        if (tid == 0) { sS = s_lt; sT = s_all; }
    }
    __syncthreads();
    int S = sS, total = sT;
    if (i < n) {
        int r = d_row[i] + S;
        d_row[i] = r;
        d_pos[i] = r;
        d_dis[i] = rsqrtf((float)(d_deg[i] + 1));   // +1 = self loop
    }
    if (i == 0) d_row[n] = total;
}

__global__ void k_place(const void* __restrict__ ei, int e, int n) {
    int i = blockIdx.x * blockDim.x + threadIdx.x;
    if (i < e) {
        int is64 = d_is64;
        int s = load_idx(ei, i, is64);                  // src = first row
        int d = load_idx(ei, (long long)e + i, is64);   // dst = second row
        if (d >= 0 && d < n && s >= 0 && s < n) {
            int p = atomicAdd(&d_pos[d], 1);
            if (p >= 0 && p < E_MAX) d_srcs[p] = s;
        }
    }
}

// ---------------- layer-1 GEMM: g1 = x @ w1 (UNscaled; dis+half convert later) ----------------
__global__ void __launch_bounds__(128) k_gemm1(const float* __restrict__ x,
                                               const float* __restrict__ w1, int n) {
    __shared__ float xs[G1_NODES][G1_PAD];
    __shared__ float ws[G1_TK * 16];
    int tid = threadIdx.x;
    int base = blockIdx.x * G1_NODES;

    unsigned long long a0[8], a1[8];
#pragma unroll
    for (int q = 0; q < 8; q++) { a0[q] = 0ull; a1[q] = 0ull; }

    for (int kt = 0; kt < 512; kt += G1_TK) {
        ((float4*)ws)[tid] = ((const float4*)(w1 + (size_t)kt * 16))[tid];
#pragma unroll
        for (int r = 0; r < 16; r++) {
            int f4 = r * 128 + tid;
            int rown = f4 >> 3;
            int col  = f4 & 7;
            int gn = base + rown;
            float4 v = make_float4(0.f, 0.f, 0.f, 0.f);
            if (gn < n) v = *(const float4*)&x[(size_t)gn * 512 + kt + col * 4];
            *(float4*)&xs[rown][col * 4] = v;
        }
        __syncthreads();
#pragma unroll
        for (int k4 = 0; k4 < G1_TK / 4; k4++) {
            float4 xa = *(const float4*)&xs[tid][k4 * 4];
            float4 xb = *(const float4*)&xs[tid + 128][k4 * 4];
#pragma unroll
            for (int kk = 0; kk < 4; kk++) {
                int k = k4 * 4 + kk;
                const ulonglong2* wp2 = (const ulonglong2*)&ws[k * 16];
                float fa = (&xa.x)[kk];
                float fb = (&xb.x)[kk];
                unsigned long long pa, pb;
                asm("mov.b64 %0, {%1, %1};" : "=l"(pa) : "f"(fa));
                asm("mov.b64 %0, {%1, %1};" : "=l"(pb) : "f"(fb));
#pragma unroll
                for (int q = 0; q < 4; q++) {
                    ulonglong2 w2v = wp2[q];
                    asm("fma.rn.f32x2 %0, %1, %2, %0;" : "+l"(a0[2 * q])     : "l"(pa), "l"(w2v.x));
                    asm("fma.rn.f32x2 %0, %1, %2, %0;" : "+l"(a0[2 * q + 1]) : "l"(pa), "l"(w2v.y));
                    asm("fma.rn.f32x2 %0, %1, %2, %0;" : "+l"(a1[2 * q])     : "l"(pb), "l"(w2v.x));
                    asm("fma.rn.f32x2 %0, %1, %2, %0;" : "+l"(a1[2 * q + 1]) : "l"(pb), "l"(w2v.y));
                }
            }
        }
        __syncthreads();
    }

#pragma unroll
    for (int half = 0; half < 2; half++) {
        int node = base + half * 128 + tid;
        if (node < n) {
            unsigned long long* ap = half ? a1 : a0;
            float outv[16];
#pragma unroll
            for (int q = 0; q < 8; q++) {
                float lo, hi;
                asm("mov.b64 {%0, %1}, %2;" : "=f"(lo), "=f"(hi) : "l"(ap[q]));
                outv[2 * q]     = lo;
                outv[2 * q + 1] = hi;
            }
#pragma unroll
            for (int q = 0; q < 4; q++)
                *(float4*)&d_g1[(size_t)node * 16 + q * 4] =
                    make_float4(outv[4 * q], outv[4 * q + 1], outv[4 * q + 2], outv[4 * q + 3]);
        }
    }
}

// ---------------- scale + convert: g1h = half(g1 * dis[node]) ----------------
__global__ void k_scale(int n) {
    int t = blockIdx.x * blockDim.x + threadIdx.x;   // one float4 -> 4 halves per thread
    int node = t >> 2;
    if (node < n) {
        float di = __ldg(&d_dis[node]);
        float4 v = *(const float4*)&d_g1[(size_t)t * 4];
        __half2 h01 = __floats2half2_rn(v.x * di, v.y * di);
        __half2 h23 = __floats2half2_rn(v.z * di, v.w * di);
        uint2 st;
        st.x = *(unsigned int*)&h01;
        st.y = *(unsigned int*)&h23;
        *(uint2*)&d_g1h[(size_t)t * 4] = st;
    }
}

// ---------------- gather 1: 8 threads/node, half features, fused GEMM2 ----------------
__global__ void k_gather1(const float* __restrict__ b1,
                          const float* __restrict__ w2, int n) {
    __shared__ float w2s[256];
    if (threadIdx.x < 256) w2s[threadIdx.x] = w2[threadIdx.x];
    __syncthreads();

    int t = blockIdx.x * blockDim.x + threadIdx.x;
    int node = t >> 3, c = t & 3, h = (t >> 2) & 1;
    bool act = node < n;
    int nc = act ? node : (n - 1);

    int rs = __ldg(&d_row[nc]), re = __ldg(&d_row[nc + 1]);
    float di = __ldg(&d_dis[nc]);
    float ax = 0.f, ay = 0.f, az = 0.f, aw = 0.f;
    if (h == 0) {
        uint2 raw = *(const uint2*)&d_g1h[(size_t)nc * 16 + c * 4];
        float2 lo = __half22float2(*(__half2*)&raw.x);
        float2 hi = __half22float2(*(__half2*)&raw.y);
        ax = lo.x; ay = lo.y; az = hi.x; aw = hi.y;
    }
#pragma unroll 4
    for (int e2 = rs + h; e2 < re; e2 += 2) {
        int s = __ldg(&d_srcs[e2]);
        uint2 raw = *(const uint2*)&d_g1h[(size_t)s * 16 + c * 4];
        float2 lo = __half22float2(*(__half2*)&raw.x);
        float2 hi = __half22float2(*(__half2*)&raw.y);
        ax += lo.x; ay += lo.y; az += hi.x; aw += hi.y;
    }
    ax += __shfl_xor_sync(0xffffffffu, ax, 4);
    ay += __shfl_xor_sync(0xffffffffu, ay, 4);
    az += __shfl_xor_sync(0xffffffffu, az, 4);
    aw += __shfl_xor_sync(0xffffffffu, aw, 4);

    float4 b4 = *(const float4*)&b1[c * 4];
    float al[4];
    al[0] = fmaxf(fmaf(ax, di, b4.x), 0.f);
    al[1] = fmaxf(fmaf(ay, di, b4.y), 0.f);
    al[2] = fmaxf(fmaf(az, di, b4.z), 0.f);
    al[3] = fmaxf(fmaf(aw, di, b4.w), 0.f);

    int lane = threadIdx.x & 31;
    int lb = lane & ~3;
    float h2[4] = {0.f, 0.f, 0.f, 0.f};
#pragma unroll
    for (int j = 0; j < 16; j++) {
        float aj = __shfl_sync(0xffffffffu, al[j & 3], lb + (j >> 2));
#pragma unroll
        for (int q = 0; q < 4; q++)
            h2[q] = fmaf(aj, w2s[j * 16 + c * 4 + q], h2[q]);
    }
    if (act && h == 0) {
        __half2 o01 = __floats2half2_rn(h2[0] * di, h2[1] * di);
        __half2 o23 = __floats2half2_rn(h2[2] * di, h2[3] * di);
        uint2 st;
        st.x = *(unsigned int*)&o01;
        st.y = *(unsigned int*)&o23;
        *(uint2*)&d_g2h[(size_t)node * 16 + c * 4] = st;
    }
}

// ---------------- gather 2: 8 threads/node, logits + log_softmax ----------------
__global__ void k_gather2(const float* __restrict__ b2, float* __restrict__ out, int n) {
    int t = blockIdx.x * blockDim.x + threadIdx.x;
    int node = t >> 3, c = t & 3, h = (t >> 2) & 1;
    bool act = node < n;
    int nc = act ? node : (n - 1);

    int rs = __ldg(&d_row[nc]), re = __ldg(&d_row[nc + 1]);
    float di = __ldg(&d_dis[nc]);
    float ax = 0.f, ay = 0.f, az = 0.f, aw = 0.f;
    if (h == 0) {
        uint2 raw = *(const uint2*)&d_g2h[(size_t)nc * 16 + c * 4];
        float2 lo = __half22float2(*(__half2*)&raw.x);
        float2 hi = __half22float2(*(__half2*)&raw.y);
        ax = lo.x; ay = lo.y; az = hi.x; aw = hi.y;
    }
#pragma unroll 4
    for (int e2 = rs + h; e2 < re; e2 += 2) {
        int s = __ldg(&d_srcs[e2]);
        uint2 raw = *(const uint2*)&d_g2h[(size_t)s * 16 + c * 4];
        float2 lo = __half22float2(*(__half2*)&raw.x);
        float2 hi = __half22float2(*(__half2*)&raw.y);
        ax += lo.x; ay += lo.y; az += hi.x; aw += hi.y;
    }
    ax += __shfl_xor_sync(0xffffffffu, ax, 4);
    ay += __shfl_xor_sync(0xffffffffu, ay, 4);
    az += __shfl_xor_sync(0xffffffffu, az, 4);
    aw += __shfl_xor_sync(0xffffffffu, aw, 4);

    float4 b4 = *(const float4*)&b2[c * 4];
    float l0 = fmaf(ax, di, b4.x);
    float l1 = fmaf(ay, di, b4.y);
    float l2 = fmaf(az, di, b4.z);
    float l3 = fmaf(aw, di, b4.w);

    float m = fmaxf(fmaxf(l0, l1), fmaxf(l2, l3));
    m = fmaxf(m, __shfl_xor_sync(0xffffffffu, m, 1));
    m = fmaxf(m, __shfl_xor_sync(0xffffffffu, m, 2));
    float s4 = expf(l0 - m) + expf(l1 - m) + expf(l2 - m) + expf(l3 - m);
    s4 += __shfl_xor_sync(0xffffffffu, s4, 1);
    s4 += __shfl_xor_sync(0xffffffffu, s4, 2);
    float lse = m + logf(s4);

    if (act && h == 0)
        *(float4*)&out[(size_t)node * 16 + c * 4] =
            make_float4(l0 - lse, l1 - lse, l2 - lse, l3 - lse);
}

// ---------------- launch (fork: gemm1+scale parallel with graph preprocessing) ----------------
extern "C" void kernel_launch(void* const* d_in, const int* in_sizes, int n_in,
                              void* d_out, int out_size) {
    static cudaStream_t s2 = nullptr;
    static cudaEvent_t ev_fork = nullptr, ev_scan = nullptr, ev_join = nullptr;
    if (s2 == nullptr) {
        cudaStreamCreateWithFlags(&s2, cudaStreamNonBlocking);
        cudaEventCreateWithFlags(&ev_fork, cudaEventDisableTiming);
        cudaEventCreateWithFlags(&ev_scan, cudaEventDisableTiming);
        cudaEventCreateWithFlags(&ev_join, cudaEventDisableTiming);
    }

    // Identify inputs by element count (robust to metadata ordering).
    const float* x = nullptr; const void* ei = nullptr;
    const float* w1 = nullptr; const float* w2 = nullptr;
    const float* b1 = nullptr; const float* b2 = nullptr;
    long long x_sz = 0, e_sz = 0;
    for (int i = 0; i < n_in; i++) {
        long long sz = in_sizes[i];
        if (sz == 16) {
            if (!b1) b1 = (const float*)d_in[i];
            else     b2 = (const float*)d_in[i];
        } else if (sz == 256) {
            w2 = (const float*)d_in[i];
        } else if (sz == 8192) {
            w1 = (const float*)d_in[i];
        } else if (sz > 8192) {
            if (!x) { x = (const float*)d_in[i]; x_sz = sz; }
            else if (sz > x_sz) { ei = (const void*)x; e_sz = x_sz;
                                  x = (const float*)d_in[i]; x_sz = sz; }
            else { ei = (const void*)d_in[i]; e_sz = sz; }
        }
    }

    float* out = (float*)d_out;
    int n = (int)(x_sz / 512);
    int e = (int)(e_sz / 2);
    if (n > N_MAX) n = N_MAX;
    if (e > E_MAX) e = E_MAX;

    int nb = (n + 1023) / 1024;

    // fork: gemm1 (independent of graph structure) on s2
    cudaEventRecord(ev_fork, 0);
    cudaStreamWaitEvent(s2, ev_fork, 0);
    k_gemm1<<<(n + G1_NODES - 1) / G1_NODES, 128, 0, s2>>>(x, w1, n);

    // preprocessing chain on the capture (default) stream
    k_init<<<(n + 255) / 256, 256>>>((const int*)ei, e, n);
    k_count<<<(e + 255) / 256, 256>>>(ei, e, n);
    k_scan_block<<<nb, 1024>>>(n);
    k_scan_add<<<(n + 255) / 256, 256>>>(n, nb);
    cudaEventRecord(ev_scan, 0);               // dis ready

    // scale (needs gemm1 + dis) overlaps place on the main stream
    cudaStreamWaitEvent(s2, ev_scan, 0);
    k_scale<<<(n * 4 + 255) / 256, 256, 0, s2>>>(n);
    cudaEventRecord(ev_join, s2);

    k_place<<<(e + 255) / 256, 256>>>(ei, e, n);

    cudaStreamWaitEvent(0, ev_join, 0);
    k_gather1<<<(n * 8 + 255) / 256, 256>>>(b1, w2, n);
    k_gather2<<<(n * 8 + 255) / 256, 256>>>(b2, out, n);
}